// round 5
// baseline (speedup 1.0000x reference)
#include <cuda_runtime.h>
#include <cstdint>

__device__ float g_pool[384 * 25088];
__device__ float g_fc6[384 * 4096];
__device__ float g_fc7[384 * 4096];

// ---------------- ROI max pool: grid(384,4), block 256 ----------------
__global__ void roipool_kernel(const float* __restrict__ x, const float* __restrict__ rois,
                               const int* __restrict__ ridx) {
    int m = blockIdx.x, cg = blockIdx.y;
    float* out = g_pool + (size_t)m * 25088 + (size_t)cg * 128 * 49;
    if (m >= 300) {
        for (int u = threadIdx.x; u < 128 * 49; u += 256) out[u] = 0.f;
        return;
    }
    float y1 = rois[m * 4 + 0], x1 = rois[m * 4 + 1];
    float y2 = rois[m * 4 + 2], x2 = rois[m * 4 + 3];
    int bi = ridx[m];
    int sh_ = (int)rintf(y1 * 0.0625f), sw_ = (int)rintf(x1 * 0.0625f);
    int eh_ = (int)rintf(y2 * 0.0625f), ew_ = (int)rintf(x2 * 0.0625f);
    // XLA rewrites divide-by-constant into multiply-by-reciprocal; mirror it exactly.
    const float INV7 = 1.0f / 7.0f;  // fl(1/7), compile-time f32 constant
    float bh = fmaxf((float)(eh_ - sh_ + 1), 1.f) * INV7;
    float bw = fmaxf((float)(ew_ - sw_ + 1), 1.f) * INV7;
    const float* fm = x + (size_t)bi * 512 * 1900;
    for (int u = threadIdx.x; u < 128 * 49; u += 256) {
        int c = cg * 128 + u / 49;
        int bin = u % 49, ph = bin / 7, pw = bin % 7;
        int hs = min(max((int)floorf((float)ph * bh) + sh_, 0), 38);
        int he = min(max((int)ceilf((float)(ph + 1) * bh) + sh_, 0), 38);
        int ws = min(max((int)floorf((float)pw * bw) + sw_, 0), 50);
        int we = min(max((int)ceilf((float)(pw + 1) * bw) + sw_, 0), 50);
        const float* fc = fm + (size_t)c * 1900;
        float mx = -1e30f;
        for (int y = hs; y < he; y++)
            for (int xx = ws; xx < we; xx++)
                mx = fmaxf(mx, fc[y * 50 + xx]);
        out[u] = (he > hs && we > ws) ? mx : 0.f;
    }
}

// ---------------- exact fp32 SGEMM: C[M,N] = A[M,K] @ B[K,N] ----------------
#define BM 64
#define BN 128
#define BK 16
__global__ void __launch_bounds__(256) sgemm_kernel(const float* __restrict__ A,
                                                    const float* __restrict__ B,
                                                    float* __restrict__ C,
                                                    int N, int K) {
    __shared__ float As[2][BK][BM];
    __shared__ float Bs[2][BK][BN + 4];

    int tid = threadIdx.x;
    int bm = blockIdx.y * BM, bn = blockIdx.x * BN;
    int tx = tid & 15, ty = tid >> 4;

    float acc[4][8];
#pragma unroll
    for (int i = 0; i < 4; i++)
#pragma unroll
        for (int j = 0; j < 8; j++) acc[i][j] = 0.f;

    int arow = tid >> 2;
    int akc  = (tid & 3) * 4;
    int brow = tid >> 5;
    int bcol = (tid & 31) * 4;

    const float* Ap = A + (size_t)(bm + arow) * K + akc;
    const float* Bp = B + (size_t)brow * N + bn + bcol;

#define LOAD(buf, k0)                                                                  \
    do {                                                                               \
        float4 a = *(const float4*)(Ap + (k0));                                        \
        As[buf][akc + 0][arow] = a.x;                                                  \
        As[buf][akc + 1][arow] = a.y;                                                  \
        As[buf][akc + 2][arow] = a.z;                                                  \
        As[buf][akc + 3][arow] = a.w;                                                  \
        *(float4*)&Bs[buf][brow][bcol]     = *(const float4*)(Bp + (size_t)(k0) * N);  \
        *(float4*)&Bs[buf][brow + 8][bcol] = *(const float4*)(Bp + (size_t)((k0) + 8) * N); \
    } while (0)

    LOAD(0, 0);
    __syncthreads();
    int nk = K / BK;
    for (int kt = 0; kt < nk; kt++) {
        int buf = kt & 1;
        if (kt + 1 < nk) LOAD(buf ^ 1, (kt + 1) * BK);
#pragma unroll
        for (int k = 0; k < BK; k++) {
            float4 av = *(const float4*)&As[buf][k][ty * 4];
            float4 b0 = *(const float4*)&Bs[buf][k][tx * 8];
            float4 b1 = *(const float4*)&Bs[buf][k][tx * 8 + 4];
            float a_[4] = { av.x, av.y, av.z, av.w };
            float b_[8] = { b0.x, b0.y, b0.z, b0.w, b1.x, b1.y, b1.z, b1.w };
#pragma unroll
            for (int i = 0; i < 4; i++)
#pragma unroll
                for (int j = 0; j < 8; j++) acc[i][j] = fmaf(a_[i], b_[j], acc[i][j]);
        }
        __syncthreads();
    }
#pragma unroll
    for (int i = 0; i < 4; i++) {
        float* Cp = C + (size_t)(bm + ty * 4 + i) * N + bn + tx * 8;
#pragma unroll
        for (int j = 0; j < 8; j++) Cp[j] = acc[i][j];
    }
#undef LOAD
}

// ---------------- bias + relu over [384,4096] ----------------
__global__ void bias_relu_kernel(float* __restrict__ X, const float* __restrict__ b) {
    int i = blockIdx.x * 256 + threadIdx.x;
    if (i < 384 * 4096) {
        float v = X[i] + b[i & 4095];
        X[i] = v > 0.f ? v : 0.f;
    }
}

// ---------------- head: deltas [300,84] then scores [300,21] ----------------
__global__ void __launch_bounds__(128) head_kernel(const float* __restrict__ Ws,
                                                   const float* __restrict__ bs,
                                                   const float* __restrict__ Wp,
                                                   const float* __restrict__ bp,
                                                   float* __restrict__ out) {
    __shared__ float s[4096];
    int r = blockIdx.x;
    const float4* f = (const float4*)(g_fc7 + (size_t)r * 4096);
    for (int i = threadIdx.x; i < 1024; i += 128) ((float4*)s)[i] = f[i];
    __syncthreads();
    int c = threadIdx.x;
    if (c >= 105) return;
    const float* W;
    int stride;
    if (c < 84) { W = Wp + c; stride = 84; }
    else        { W = Ws + (c - 84); stride = 21; }
    float acc = 0.f;
#pragma unroll 8
    for (int k = 0; k < 4096; k++) acc = fmaf(s[k], W[(size_t)k * stride], acc);
    if (c < 84) out[r * 84 + c] = acc + bp[c];
    else        out[25200 + r * 21 + (c - 84)] = acc + bs[c - 84];
}

// ---------------- launch ----------------
extern "C" void kernel_launch(void* const* d_in, const int* in_sizes, int n_in,
                              void* d_out, int out_size) {
    const float* x    = (const float*)d_in[0];
    const float* rois = (const float*)d_in[1];
    const int*   ridx = (const int*)d_in[2];
    const float* W1   = (const float*)d_in[3];
    const float* b1   = (const float*)d_in[4];
    const float* W2   = (const float*)d_in[5];
    const float* b2   = (const float*)d_in[6];
    const float* Ws   = (const float*)d_in[7];
    const float* bs   = (const float*)d_in[8];
    const float* Wp   = (const float*)d_in[9];
    const float* bp   = (const float*)d_in[10];
    float* out = (float*)d_out;

    void *pPool, *pFc6, *pFc7;
    cudaGetSymbolAddress(&pPool, g_pool);
    cudaGetSymbolAddress(&pFc6, g_fc6);
    cudaGetSymbolAddress(&pFc7, g_fc7);

    roipool_kernel<<<dim3(384, 4), 256>>>(x, rois, ridx);
    sgemm_kernel<<<dim3(4096 / BN, 384 / BM), 256>>>((const float*)pPool, W1, (float*)pFc6, 4096, 25088);
    bias_relu_kernel<<<(384 * 4096 + 255) / 256, 256>>>((float*)pFc6, b1);
    sgemm_kernel<<<dim3(4096 / BN, 384 / BM), 256>>>((const float*)pFc6, W2, (float*)pFc7, 4096, 4096);
    bias_relu_kernel<<<(384 * 4096 + 255) / 256, 256>>>((float*)pFc7, b2);
    head_kernel<<<300, 128>>>(Ws, bs, Wp, bp, out);
}

// round 7
// speedup vs baseline: 1.9894x; 1.9894x over previous
#include <cuda_runtime.h>
#include <cuda_bf16.h>
#include <mma.h>
#include <cstdint>

using namespace nvcuda;
using bf16 = __nv_bfloat16;

__device__ float g_pool[384 * 25088];
__device__ float g_fc6[384 * 4096];
__device__ float g_fc7[384 * 4096];

// ---------------- ROI max pool: grid(384,4), block 256 ----------------
__global__ void roipool_kernel(const float* __restrict__ x, const float* __restrict__ rois,
                               const int* __restrict__ ridx) {
    int m = blockIdx.x, cg = blockIdx.y;
    float* out = g_pool + (size_t)m * 25088 + (size_t)cg * 128 * 49;
    if (m >= 300) {
        for (int u = threadIdx.x; u < 128 * 49; u += 256) out[u] = 0.f;
        return;
    }
    float y1 = rois[m * 4 + 0], x1 = rois[m * 4 + 1];
    float y2 = rois[m * 4 + 2], x2 = rois[m * 4 + 3];
    int bi = ridx[m];
    int sh_ = (int)rintf(y1 * 0.0625f), sw_ = (int)rintf(x1 * 0.0625f);
    int eh_ = (int)rintf(y2 * 0.0625f), ew_ = (int)rintf(x2 * 0.0625f);
    const float INV7 = 1.0f / 7.0f;   // XLA reciprocal-multiply; must match bit-exactly
    float bh = fmaxf((float)(eh_ - sh_ + 1), 1.f) * INV7;
    float bw = fmaxf((float)(ew_ - sw_ + 1), 1.f) * INV7;
    const float* fm = x + (size_t)bi * 512 * 1900;
    for (int u = threadIdx.x; u < 128 * 49; u += 256) {
        int c = cg * 128 + u / 49;
        int bin = u % 49, ph = bin / 7, pw = bin % 7;
        int hs = min(max((int)floorf((float)ph * bh) + sh_, 0), 38);
        int he = min(max((int)ceilf((float)(ph + 1) * bh) + sh_, 0), 38);
        int ws = min(max((int)floorf((float)pw * bw) + sw_, 0), 50);
        int we = min(max((int)ceilf((float)(pw + 1) * bw) + sw_, 0), 50);
        const float* fc = fm + (size_t)c * 1900;
        float mx = -1e30f;
        for (int y = hs; y < he; y++)
            for (int xx = ws; xx < we; xx++)
                mx = fmaxf(mx, fc[y * 50 + xx]);
        out[u] = (he > hs && we > ws) ? mx : 0.f;
    }
}

// ---------------- split-bf16 wmma GEMM: C[M,N] = A[M,K] @ B[K,N] ----------------
// BM=128, BN=128, BK=32, 256 threads. a = a_hi + a_lo; acc += hh + hl + lh.
#define BK 32
#define A_LD 40     // padded leading dim (elements), 80B rows (16B-multiple)
#define B_LD 136    // 272B rows
#define A_PLANE (128 * A_LD)
#define B_PLANE (32 * B_LD)

__device__ __forceinline__ uint32_t pack_hi(float f0, float f1) {
    uint32_t r;
    asm("cvt.rn.bf16x2.f32 %0, %1, %2;" : "=r"(r) : "f"(f1), "f"(f0));  // low=bf16(f0)
    return r;
}

__global__ void __launch_bounds__(256, 1) gemm_wmma_kernel(const float* __restrict__ A,
                                                           const float* __restrict__ B,
                                                           float* __restrict__ C,
                                                           int K) {
    extern __shared__ char smraw[];
    bf16* smA = (bf16*)smraw;                       // [2 stages][2 types][A_PLANE]
    bf16* smB = smA + 4 * A_PLANE;                  // [2 stages][2 types][B_PLANE]

    int tid = threadIdx.x, wid = tid >> 5;
    int wm = wid & 3, wn = wid >> 2;
    int n0 = blockIdx.x * 128, bm = blockIdx.y * 128;

    wmma::fragment<wmma::accumulator, 16, 16, 16, float> acc[2][4];
#pragma unroll
    for (int i = 0; i < 2; i++)
#pragma unroll
        for (int j = 0; j < 4; j++) wmma::fill_fragment(acc[i][j], 0.f);

#define LOADSTS(buf, kc0)                                                              \
    do {                                                                               \
        bf16* Ah = smA + ((buf) * 2 + 0) * A_PLANE;                                    \
        bf16* Al = smA + ((buf) * 2 + 1) * A_PLANE;                                    \
        bf16* Bh = smB + ((buf) * 2 + 0) * B_PLANE;                                    \
        bf16* Bl = smB + ((buf) * 2 + 1) * B_PLANE;                                    \
        _Pragma("unroll")                                                              \
        for (int i = 0; i < 4; i++) {                                                  \
            int idx = tid + (i << 8);                                                  \
            int row = idx >> 3, c4 = idx & 7;                                          \
            float4 a = *(const float4*)(A + (size_t)(bm + row) * K + (kc0) + c4 * 4);  \
            uint32_t h01 = pack_hi(a.x, a.y), h23 = pack_hi(a.z, a.w);                 \
            float l0 = a.x - __uint_as_float(h01 << 16);                               \
            float l1 = a.y - __uint_as_float(h01 & 0xFFFF0000u);                       \
            float l2 = a.z - __uint_as_float(h23 << 16);                               \
            float l3 = a.w - __uint_as_float(h23 & 0xFFFF0000u);                       \
            *(uint2*)(Ah + row * A_LD + c4 * 4) = make_uint2(h01, h23);                \
            *(uint2*)(Al + row * A_LD + c4 * 4) = make_uint2(pack_hi(l0, l1), pack_hi(l2, l3)); \
        }                                                                              \
        _Pragma("unroll")                                                              \
        for (int i = 0; i < 4; i++) {                                                  \
            int idx = tid + (i << 8);                                                  \
            int row = idx >> 5, c4 = idx & 31;                                         \
            float4 b = *(const float4*)(B + (size_t)((kc0) + row) * 4096 + n0 + c4 * 4); \
            uint32_t h01 = pack_hi(b.x, b.y), h23 = pack_hi(b.z, b.w);                 \
            float l0 = b.x - __uint_as_float(h01 << 16);                               \
            float l1 = b.y - __uint_as_float(h01 & 0xFFFF0000u);                       \
            float l2 = b.z - __uint_as_float(h23 << 16);                               \
            float l3 = b.w - __uint_as_float(h23 & 0xFFFF0000u);                       \
            *(uint2*)(Bh + row * B_LD + c4 * 4) = make_uint2(h01, h23);                \
            *(uint2*)(Bl + row * B_LD + c4 * 4) = make_uint2(pack_hi(l0, l1), pack_hi(l2, l3)); \
        }                                                                              \
    } while (0)

    LOADSTS(0, 0);
    __syncthreads();
    int nk = K / BK;
    for (int kt = 0; kt < nk; kt++) {
        int buf = kt & 1;
        if (kt + 1 < nk) LOADSTS(buf ^ 1, (kt + 1) * BK);

        const bf16* Ah = smA + (buf * 2 + 0) * A_PLANE;
        const bf16* Al = smA + (buf * 2 + 1) * A_PLANE;
        const bf16* Bh = smB + (buf * 2 + 0) * B_PLANE;
        const bf16* Bl = smB + (buf * 2 + 1) * B_PLANE;
#pragma unroll
        for (int ks = 0; ks < 2; ks++) {
            wmma::fragment<wmma::matrix_a, 16, 16, 16, bf16, wmma::row_major> a_hi[2], a_lo[2];
            wmma::fragment<wmma::matrix_b, 16, 16, 16, bf16, wmma::row_major> b_hi[4], b_lo[4];
#pragma unroll
            for (int i = 0; i < 2; i++) {
                wmma::load_matrix_sync(a_hi[i], Ah + (wm * 32 + i * 16) * A_LD + ks * 16, A_LD);
                wmma::load_matrix_sync(a_lo[i], Al + (wm * 32 + i * 16) * A_LD + ks * 16, A_LD);
            }
#pragma unroll
            for (int j = 0; j < 4; j++) {
                wmma::load_matrix_sync(b_hi[j], Bh + (ks * 16) * B_LD + wn * 64 + j * 16, B_LD);
                wmma::load_matrix_sync(b_lo[j], Bl + (ks * 16) * B_LD + wn * 64 + j * 16, B_LD);
            }
#pragma unroll
            for (int i = 0; i < 2; i++)
#pragma unroll
                for (int j = 0; j < 4; j++) {
                    wmma::mma_sync(acc[i][j], a_hi[i], b_hi[j], acc[i][j]);
                    wmma::mma_sync(acc[i][j], a_hi[i], b_lo[j], acc[i][j]);
                    wmma::mma_sync(acc[i][j], a_lo[i], b_hi[j], acc[i][j]);
                }
        }
        __syncthreads();
    }
#pragma unroll
    for (int i = 0; i < 2; i++)
#pragma unroll
        for (int j = 0; j < 4; j++)
            wmma::store_matrix_sync(C + (size_t)(bm + wm * 32 + i * 16) * 4096 + n0 + wn * 64 + j * 16,
                                    acc[i][j], 4096, wmma::mem_row_major);
#undef LOADSTS
}

// ---------------- bias + relu in place over [384,4096] ----------------
__global__ void bias_relu_kernel(float* __restrict__ X, const float* __restrict__ b) {
    int i = blockIdx.x * 256 + threadIdx.x;
    float v = X[i] + b[i & 4095];
    X[i] = v > 0.f ? v : 0.f;
}

// ---------------- head: 4 rows per block ----------------
__global__ void __launch_bounds__(128) head4_kernel(const float* __restrict__ fc7,
                                                    const float* __restrict__ Ws,
                                                    const float* __restrict__ bs,
                                                    const float* __restrict__ Wp,
                                                    const float* __restrict__ bp,
                                                    float* __restrict__ out) {
    extern __shared__ float s[];            // 4 * 4096
    int r0 = blockIdx.x * 4;
    const float4* src = (const float4*)(fc7 + (size_t)r0 * 4096);
    for (int i = threadIdx.x; i < 4096; i += 128) ((float4*)s)[i] = src[i];
    __syncthreads();
    int c = threadIdx.x;
    if (c >= 105) return;
    const float* W;
    int stride;
    float bias;
    if (c < 84) { W = Wp + c; stride = 84; bias = bp[c]; }
    else        { W = Ws + (c - 84); stride = 21; bias = bs[c - 84]; }
    float a0 = 0.f, a1 = 0.f, a2 = 0.f, a3 = 0.f;
#pragma unroll 4
    for (int k = 0; k < 4096; k++) {
        float w = W[(size_t)k * stride];
        a0 = fmaf(s[k], w, a0);
        a1 = fmaf(s[4096 + k], w, a1);
        a2 = fmaf(s[8192 + k], w, a2);
        a3 = fmaf(s[12288 + k], w, a3);
    }
    if (c < 84) {
        out[(r0 + 0) * 84 + c] = a0 + bias;
        out[(r0 + 1) * 84 + c] = a1 + bias;
        out[(r0 + 2) * 84 + c] = a2 + bias;
        out[(r0 + 3) * 84 + c] = a3 + bias;
    } else {
        int cc = c - 84;
        out[25200 + (r0 + 0) * 21 + cc] = a0 + bias;
        out[25200 + (r0 + 1) * 21 + cc] = a1 + bias;
        out[25200 + (r0 + 2) * 21 + cc] = a2 + bias;
        out[25200 + (r0 + 3) * 21 + cc] = a3 + bias;
    }
}

// ---------------- launch ----------------
extern "C" void kernel_launch(void* const* d_in, const int* in_sizes, int n_in,
                              void* d_out, int out_size) {
    const float* x    = (const float*)d_in[0];
    const float* rois = (const float*)d_in[1];
    const int*   ridx = (const int*)d_in[2];
    const float* W1   = (const float*)d_in[3];
    const float* b1   = (const float*)d_in[4];
    const float* W2   = (const float*)d_in[5];
    const float* b2   = (const float*)d_in[6];
    const float* Ws   = (const float*)d_in[7];
    const float* bs   = (const float*)d_in[8];
    const float* Wp   = (const float*)d_in[9];
    const float* bp   = (const float*)d_in[10];
    float* out = (float*)d_out;

    void *pPool, *pFc6, *pFc7;
    cudaGetSymbolAddress(&pPool, g_pool);
    cudaGetSymbolAddress(&pFc6, g_fc6);
    cudaGetSymbolAddress(&pFc7, g_fc7);

    const int GEMM_SMEM = (4 * A_PLANE + 4 * B_PLANE) * 2;   // bf16 bytes = 75,776
    cudaFuncSetAttribute(gemm_wmma_kernel, cudaFuncAttributeMaxDynamicSharedMemorySize, GEMM_SMEM);
    cudaFuncSetAttribute(head4_kernel, cudaFuncAttributeMaxDynamicSharedMemorySize, 65536);

    roipool_kernel<<<dim3(384, 4), 256>>>(x, rois, ridx);
    gemm_wmma_kernel<<<dim3(32, 3), 256, GEMM_SMEM>>>((const float*)pPool, W1, (float*)pFc6, 25088);
    bias_relu_kernel<<<(384 * 4096) / 256, 256>>>((float*)pFc6, b1);
    gemm_wmma_kernel<<<dim3(32, 3), 256, GEMM_SMEM>>>((const float*)pFc6, W2, (float*)pFc7, 4096);
    bias_relu_kernel<<<(384 * 4096) / 256, 256>>>((float*)pFc7, b2);
    head4_kernel<<<75, 128, 65536>>>((const float*)pFc7, Ws, bs, Wp, bp, out);
}

// round 8
// speedup vs baseline: 2.1159x; 1.0636x over previous
#include <cuda_runtime.h>
#include <cuda_bf16.h>
#include <mma.h>
#include <cstdint>

using namespace nvcuda;
using bf16 = __nv_bfloat16;

__device__ float g_pool[384 * 25088];
__device__ float g_fc6[384 * 4096];
__device__ float g_fc7[384 * 4096];

// ---------------- ROI max pool: grid(384,4), block 256, 4-channel streams ----------------
__global__ void roipool_kernel(const float* __restrict__ x, const float* __restrict__ rois,
                               const int* __restrict__ ridx) {
    int m = blockIdx.x, cg = blockIdx.y;
    float* out = g_pool + (size_t)m * 25088 + (size_t)cg * 128 * 49;
    if (m >= 300) {
        for (int u = threadIdx.x; u < 128 * 49; u += 256) out[u] = 0.f;
        return;
    }
    float y1 = rois[m * 4 + 0], x1 = rois[m * 4 + 1];
    float y2 = rois[m * 4 + 2], x2 = rois[m * 4 + 3];
    int bi = ridx[m];
    int sh_ = (int)rintf(y1 * 0.0625f), sw_ = (int)rintf(x1 * 0.0625f);
    int eh_ = (int)rintf(y2 * 0.0625f), ew_ = (int)rintf(x2 * 0.0625f);
    const float INV7 = 1.0f / 7.0f;   // XLA reciprocal-multiply; must match bit-exactly
    float bh = fmaxf((float)(eh_ - sh_ + 1), 1.f) * INV7;
    float bw = fmaxf((float)(ew_ - sw_ + 1), 1.f) * INV7;
    const float* fm = x + (size_t)bi * 512 * 1900;
    // 49 bins x 32 channel-quads = 1568 items; each item scans 4 channels in parallel
    for (int u = threadIdx.x; u < 1568; u += 256) {
        int bin = u % 49, cq = u / 49;
        int ph = bin / 7, pw = bin % 7;
        int hs = min(max((int)floorf((float)ph * bh) + sh_, 0), 38);
        int he = min(max((int)ceilf((float)(ph + 1) * bh) + sh_, 0), 38);
        int ws = min(max((int)floorf((float)pw * bw) + sw_, 0), 50);
        int we = min(max((int)ceilf((float)(pw + 1) * bw) + sw_, 0), 50);
        int c = cg * 128 + cq * 4;
        const float* f0 = fm + (size_t)c * 1900;
        const float* f1 = f0 + 1900;
        const float* f2 = f1 + 1900;
        const float* f3 = f2 + 1900;
        float m0 = -1e30f, m1 = -1e30f, m2 = -1e30f, m3 = -1e30f;
        for (int y = hs; y < he; y++)
            for (int xx = ws; xx < we; xx++) {
                int idx = y * 50 + xx;
                m0 = fmaxf(m0, f0[idx]);
                m1 = fmaxf(m1, f1[idx]);
                m2 = fmaxf(m2, f2[idx]);
                m3 = fmaxf(m3, f3[idx]);
            }
        bool ok = (he > hs) && (we > ws);
        out[(cq * 4 + 0) * 49 + bin] = ok ? m0 : 0.f;
        out[(cq * 4 + 1) * 49 + bin] = ok ? m1 : 0.f;
        out[(cq * 4 + 2) * 49 + bin] = ok ? m2 : 0.f;
        out[(cq * 4 + 3) * 49 + bin] = ok ? m3 : 0.f;
    }
}

// ---------------- split-bf16 wmma GEMM: C[M,N] = A[M,K] @ B[K,N] ----------------
// BM=64, BN=128, BK=32, 256 threads, 2 CTAs/SM. a = a_hi + a_lo; acc += hh + hl + lh.
#define BK 32
#define A_LD 40
#define B_LD 136
#define A_PLANE (64 * A_LD)    // 2560 elems
#define B_PLANE (32 * B_LD)    // 4352 elems

__device__ __forceinline__ uint32_t pack_hi(float f0, float f1) {
    uint32_t r;
    asm("cvt.rn.bf16x2.f32 %0, %1, %2;" : "=r"(r) : "f"(f1), "f"(f0));  // low=bf16(f0)
    return r;
}

__global__ void __launch_bounds__(256, 2) gemm_wmma_kernel(const float* __restrict__ A,
                                                           const float* __restrict__ B,
                                                           float* __restrict__ C,
                                                           int K) {
    extern __shared__ char smraw[];
    bf16* smA = (bf16*)smraw;                       // [2 stages][2 types][A_PLANE]
    bf16* smB = smA + 4 * A_PLANE;                  // [2 stages][2 types][B_PLANE]

    int tid = threadIdx.x, wid = tid >> 5;
    int wm = wid >> 2, wn = wid & 3;                // 2 x 4 warps, each 32x32
    int n0 = blockIdx.x * 128, bm = blockIdx.y * 64;

    wmma::fragment<wmma::accumulator, 16, 16, 16, float> acc[2][2];
#pragma unroll
    for (int i = 0; i < 2; i++)
#pragma unroll
        for (int j = 0; j < 2; j++) wmma::fill_fragment(acc[i][j], 0.f);

#define LOADSTS(buf, kc0)                                                              \
    do {                                                                               \
        bf16* Ah = smA + ((buf) * 2 + 0) * A_PLANE;                                    \
        bf16* Al = smA + ((buf) * 2 + 1) * A_PLANE;                                    \
        bf16* Bh = smB + ((buf) * 2 + 0) * B_PLANE;                                    \
        bf16* Bl = smB + ((buf) * 2 + 1) * B_PLANE;                                    \
        _Pragma("unroll")                                                              \
        for (int i = 0; i < 2; i++) {                                                  \
            int idx = tid + (i << 8);                                                  \
            int row = idx >> 3, c4 = idx & 7;                                          \
            float4 a = *(const float4*)(A + (size_t)(bm + row) * K + (kc0) + c4 * 4);  \
            uint32_t h01 = pack_hi(a.x, a.y), h23 = pack_hi(a.z, a.w);                 \
            float l0 = a.x - __uint_as_float(h01 << 16);                               \
            float l1 = a.y - __uint_as_float(h01 & 0xFFFF0000u);                       \
            float l2 = a.z - __uint_as_float(h23 << 16);                               \
            float l3 = a.w - __uint_as_float(h23 & 0xFFFF0000u);                       \
            *(uint2*)(Ah + row * A_LD + c4 * 4) = make_uint2(h01, h23);                \
            *(uint2*)(Al + row * A_LD + c4 * 4) = make_uint2(pack_hi(l0, l1), pack_hi(l2, l3)); \
        }                                                                              \
        _Pragma("unroll")                                                              \
        for (int i = 0; i < 4; i++) {                                                  \
            int idx = tid + (i << 8);                                                  \
            int row = idx >> 5, c4 = idx & 31;                                         \
            float4 b = *(const float4*)(B + (size_t)((kc0) + row) * 4096 + n0 + c4 * 4); \
            uint32_t h01 = pack_hi(b.x, b.y), h23 = pack_hi(b.z, b.w);                 \
            float l0 = b.x - __uint_as_float(h01 << 16);                               \
            float l1 = b.y - __uint_as_float(h01 & 0xFFFF0000u);                       \
            float l2 = b.z - __uint_as_float(h23 << 16);                               \
            float l3 = b.w - __uint_as_float(h23 & 0xFFFF0000u);                       \
            *(uint2*)(Bh + row * B_LD + c4 * 4) = make_uint2(h01, h23);                \
            *(uint2*)(Bl + row * B_LD + c4 * 4) = make_uint2(pack_hi(l0, l1), pack_hi(l2, l3)); \
        }                                                                              \
    } while (0)

    LOADSTS(0, 0);
    __syncthreads();
    int nk = K / BK;
    for (int kt = 0; kt < nk; kt++) {
        int buf = kt & 1;
        if (kt + 1 < nk) LOADSTS(buf ^ 1, (kt + 1) * BK);

        const bf16* Ah = smA + (buf * 2 + 0) * A_PLANE;
        const bf16* Al = smA + (buf * 2 + 1) * A_PLANE;
        const bf16* Bh = smB + (buf * 2 + 0) * B_PLANE;
        const bf16* Bl = smB + (buf * 2 + 1) * B_PLANE;
#pragma unroll
        for (int ks = 0; ks < 2; ks++) {
            wmma::fragment<wmma::matrix_a, 16, 16, 16, bf16, wmma::row_major> a_hi[2], a_lo[2];
            wmma::fragment<wmma::matrix_b, 16, 16, 16, bf16, wmma::row_major> b_hi[2], b_lo[2];
#pragma unroll
            for (int i = 0; i < 2; i++) {
                wmma::load_matrix_sync(a_hi[i], Ah + (wm * 32 + i * 16) * A_LD + ks * 16, A_LD);
                wmma::load_matrix_sync(a_lo[i], Al + (wm * 32 + i * 16) * A_LD + ks * 16, A_LD);
            }
#pragma unroll
            for (int j = 0; j < 2; j++) {
                wmma::load_matrix_sync(b_hi[j], Bh + (ks * 16) * B_LD + wn * 32 + j * 16, B_LD);
                wmma::load_matrix_sync(b_lo[j], Bl + (ks * 16) * B_LD + wn * 32 + j * 16, B_LD);
            }
#pragma unroll
            for (int i = 0; i < 2; i++)
#pragma unroll
                for (int j = 0; j < 2; j++) {
                    wmma::mma_sync(acc[i][j], a_hi[i], b_hi[j], acc[i][j]);
                    wmma::mma_sync(acc[i][j], a_hi[i], b_lo[j], acc[i][j]);
                    wmma::mma_sync(acc[i][j], a_lo[i], b_hi[j], acc[i][j]);
                }
        }
        __syncthreads();
    }
#pragma unroll
    for (int i = 0; i < 2; i++)
#pragma unroll
        for (int j = 0; j < 2; j++)
            wmma::store_matrix_sync(C + (size_t)(bm + wm * 32 + i * 16) * 4096 + n0 + wn * 32 + j * 16,
                                    acc[i][j], 4096, wmma::mem_row_major);
#undef LOADSTS
}

// ---------------- bias + relu in place over [384,4096] ----------------
__global__ void bias_relu_kernel(float* __restrict__ X, const float* __restrict__ b) {
    int i = blockIdx.x * 256 + threadIdx.x;
    float v = X[i] + b[i & 4095];
    X[i] = v > 0.f ? v : 0.f;
}

// ---------------- head: 4 rows per block ----------------
__global__ void __launch_bounds__(128) head4_kernel(const float* __restrict__ fc7,
                                                    const float* __restrict__ Ws,
                                                    const float* __restrict__ bs,
                                                    const float* __restrict__ Wp,
                                                    const float* __restrict__ bp,
                                                    float* __restrict__ out) {
    extern __shared__ float s[];            // 4 * 4096
    int r0 = blockIdx.x * 4;
    const float4* src = (const float4*)(fc7 + (size_t)r0 * 4096);
    for (int i = threadIdx.x; i < 4096; i += 128) ((float4*)s)[i] = src[i];
    __syncthreads();
    int c = threadIdx.x;
    if (c >= 105) return;
    const float* W;
    int stride;
    float bias;
    if (c < 84) { W = Wp + c; stride = 84; bias = bp[c]; }
    else        { W = Ws + (c - 84); stride = 21; bias = bs[c - 84]; }
    float a0 = 0.f, a1 = 0.f, a2 = 0.f, a3 = 0.f;
#pragma unroll 4
    for (int k = 0; k < 4096; k++) {
        float w = W[(size_t)k * stride];
        a0 = fmaf(s[k], w, a0);
        a1 = fmaf(s[4096 + k], w, a1);
        a2 = fmaf(s[8192 + k], w, a2);
        a3 = fmaf(s[12288 + k], w, a3);
    }
    if (c < 84) {
        out[(r0 + 0) * 84 + c] = a0 + bias;
        out[(r0 + 1) * 84 + c] = a1 + bias;
        out[(r0 + 2) * 84 + c] = a2 + bias;
        out[(r0 + 3) * 84 + c] = a3 + bias;
    } else {
        int cc = c - 84;
        out[25200 + (r0 + 0) * 21 + cc] = a0 + bias;
        out[25200 + (r0 + 1) * 21 + cc] = a1 + bias;
        out[25200 + (r0 + 2) * 21 + cc] = a2 + bias;
        out[25200 + (r0 + 3) * 21 + cc] = a3 + bias;
    }
}

// ---------------- launch ----------------
extern "C" void kernel_launch(void* const* d_in, const int* in_sizes, int n_in,
                              void* d_out, int out_size) {
    const float* x    = (const float*)d_in[0];
    const float* rois = (const float*)d_in[1];
    const int*   ridx = (const int*)d_in[2];
    const float* W1   = (const float*)d_in[3];
    const float* b1   = (const float*)d_in[4];
    const float* W2   = (const float*)d_in[5];
    const float* b2   = (const float*)d_in[6];
    const float* Ws   = (const float*)d_in[7];
    const float* bs   = (const float*)d_in[8];
    const float* Wp   = (const float*)d_in[9];
    const float* bp   = (const float*)d_in[10];
    float* out = (float*)d_out;

    void *pPool, *pFc6, *pFc7;
    cudaGetSymbolAddress(&pPool, g_pool);
    cudaGetSymbolAddress(&pFc6, g_fc6);
    cudaGetSymbolAddress(&pFc7, g_fc7);

    const int GEMM_SMEM = (4 * A_PLANE + 4 * B_PLANE) * 2;   // 55,296 bytes
    cudaFuncSetAttribute(gemm_wmma_kernel, cudaFuncAttributeMaxDynamicSharedMemorySize, GEMM_SMEM);
    cudaFuncSetAttribute(head4_kernel, cudaFuncAttributeMaxDynamicSharedMemorySize, 65536);

    roipool_kernel<<<dim3(384, 4), 256>>>(x, rois, ridx);
    gemm_wmma_kernel<<<dim3(32, 6), 256, GEMM_SMEM>>>((const float*)pPool, W1, (float*)pFc6, 25088);
    bias_relu_kernel<<<(384 * 4096) / 256, 256>>>((float*)pFc6, b1);
    gemm_wmma_kernel<<<dim3(32, 6), 256, GEMM_SMEM>>>((const float*)pFc6, W2, (float*)pFc7, 4096);
    bias_relu_kernel<<<(384 * 4096) / 256, 256>>>((float*)pFc7, b2);
    head4_kernel<<<75, 128, 65536>>>((const float*)pFc7, Ws, bs, Wp, bp, out);
}

// round 9
// speedup vs baseline: 2.4434x; 1.1548x over previous
#include <cuda_runtime.h>
#include <cuda_bf16.h>
#include <mma.h>
#include <cstdint>

using namespace nvcuda;
using bf16 = __nv_bfloat16;

// ---------------- scratch (device globals; no allocs) ----------------
__device__ bf16  g_poolh[384 * 25088];
__device__ bf16  g_pooll[384 * 25088];
__device__ bf16  g_W1h[25088 * 4096];
__device__ bf16  g_W1l[25088 * 4096];
__device__ bf16  g_W2h[4096 * 4096];
__device__ bf16  g_W2l[4096 * 4096];
__device__ bf16  g_fc6h[384 * 4096];
__device__ bf16  g_fc6l[384 * 4096];
__device__ float g_fc7[384 * 4096];
__device__ float g_part[2 * 384 * 4096];

__device__ __forceinline__ uint32_t pack_hi(float f0, float f1) {
    uint32_t r;
    asm("cvt.rn.bf16x2.f32 %0, %1, %2;" : "=r"(r) : "f"(f1), "f"(f0));  // low=bf16(f0)
    return r;
}

// ---------------- weight fp32 -> bf16 hi/lo planes ----------------
__global__ void convW_kernel(const float* __restrict__ W, bf16* __restrict__ Wh,
                             bf16* __restrict__ Wl, int n4) {
    int i = blockIdx.x * 256 + threadIdx.x;
    if (i >= n4) return;
    float4 w = ((const float4*)W)[i];
    uint32_t h01 = pack_hi(w.x, w.y), h23 = pack_hi(w.z, w.w);
    float l0 = w.x - __uint_as_float(h01 << 16);
    float l1 = w.y - __uint_as_float(h01 & 0xFFFF0000u);
    float l2 = w.z - __uint_as_float(h23 << 16);
    float l3 = w.w - __uint_as_float(h23 & 0xFFFF0000u);
    ((uint2*)Wh)[i] = make_uint2(h01, h23);
    ((uint2*)Wl)[i] = make_uint2(pack_hi(l0, l1), pack_hi(l2, l3));
}

// ---------------- ROI max pool -> bf16 hi/lo planes ----------------
__global__ void roipool_kernel(const float* __restrict__ x, const float* __restrict__ rois,
                               const int* __restrict__ ridx) {
    int m = blockIdx.x, cg = blockIdx.y;
    size_t ob = (size_t)m * 25088 + (size_t)cg * 128 * 49;
    if (m >= 300) {
        for (int u = threadIdx.x; u < 128 * 49; u += 256) {
            g_poolh[ob + u] = __float2bfloat16_rn(0.f);
            g_pooll[ob + u] = __float2bfloat16_rn(0.f);
        }
        return;
    }
    float y1 = rois[m * 4 + 0], x1 = rois[m * 4 + 1];
    float y2 = rois[m * 4 + 2], x2 = rois[m * 4 + 3];
    int bi = ridx[m];
    int sh_ = (int)rintf(y1 * 0.0625f), sw_ = (int)rintf(x1 * 0.0625f);
    int eh_ = (int)rintf(y2 * 0.0625f), ew_ = (int)rintf(x2 * 0.0625f);
    const float INV7 = 1.0f / 7.0f;   // XLA reciprocal-multiply; bit-exact match required
    float bh = fmaxf((float)(eh_ - sh_ + 1), 1.f) * INV7;
    float bw = fmaxf((float)(ew_ - sw_ + 1), 1.f) * INV7;
    const float* fm = x + (size_t)bi * 512 * 1900;
    for (int u = threadIdx.x; u < 1568; u += 256) {
        int bin = u % 49, cq = u / 49;
        int ph = bin / 7, pw = bin % 7;
        int hs = min(max((int)floorf((float)ph * bh) + sh_, 0), 38);
        int he = min(max((int)ceilf((float)(ph + 1) * bh) + sh_, 0), 38);
        int ws = min(max((int)floorf((float)pw * bw) + sw_, 0), 50);
        int we = min(max((int)ceilf((float)(pw + 1) * bw) + sw_, 0), 50);
        int c = cg * 128 + cq * 4;
        const float* f0 = fm + (size_t)c * 1900;
        float m0 = -1e30f, m1 = -1e30f, m2 = -1e30f, m3 = -1e30f;
        for (int y = hs; y < he; y++)
            for (int xx = ws; xx < we; xx++) {
                int idx = y * 50 + xx;
                m0 = fmaxf(m0, f0[idx]);
                m1 = fmaxf(m1, f0[idx + 1900]);
                m2 = fmaxf(m2, f0[idx + 3800]);
                m3 = fmaxf(m3, f0[idx + 5700]);
            }
        bool ok = (he > hs) && (we > ws);
        float v[4] = { ok ? m0 : 0.f, ok ? m1 : 0.f, ok ? m2 : 0.f, ok ? m3 : 0.f };
#pragma unroll
        for (int i = 0; i < 4; i++) {
            bf16 h = __float2bfloat16_rn(v[i]);
            g_poolh[ob + (cq * 4 + i) * 49 + bin] = h;
            g_pooll[ob + (cq * 4 + i) * 49 + bin] = __float2bfloat16_rn(v[i] - __bfloat162float(h));
        }
    }
}

// ---------------- split-bf16 wmma GEMM with K-split ----------------
// part[z] += A[bm:bm+64, z*Kper + ...] @ B[..., n0:n0+128]; planes pre-split.
#define A_LD 40
#define B_LD 136
#define A_PLANE (64 * A_LD)     // 2560 elems per plane
#define B_PLANE (32 * B_LD)     // 4352
#define STAGE_ELEMS (2 * A_PLANE + 2 * B_PLANE)   // 13824 elems = 27648 B

__global__ void __launch_bounds__(256, 3) gemm_wmma_kernel(
        const bf16* __restrict__ Ah, const bf16* __restrict__ Al,
        const bf16* __restrict__ Bh, const bf16* __restrict__ Bl,
        float* __restrict__ part, int K, int Kper) {
    extern __shared__ char smraw[];
    bf16* sm = (bf16*)smraw;

    int tid = threadIdx.x, wid = tid >> 5;
    int wm = wid >> 2, wn = wid & 3;              // 2 x 4 warps, each 32x32
    int n0 = blockIdx.x * 128, bm = blockIdx.y * 64;
    int kbase = blockIdx.z * Kper;
    float* C = part + (size_t)blockIdx.z * 384 * 4096;

    int arow = tid >> 2, akq = tid & 3;           // A copy map

    wmma::fragment<wmma::accumulator, 16, 16, 16, float> acc[2][2];
#pragma unroll
    for (int i = 0; i < 2; i++)
#pragma unroll
        for (int j = 0; j < 2; j++) wmma::fill_fragment(acc[i][j], 0.f);

#define LOADCPY(buf, kc0)                                                              \
    do {                                                                               \
        bf16* st = sm + (buf) * STAGE_ELEMS;                                           \
        size_t aoff = (size_t)(bm + arow) * K + (kc0) + akq * 8;                       \
        *(uint4*)(st + arow * A_LD + akq * 8)        = *(const uint4*)(Ah + aoff);     \
        *(uint4*)(st + (64 + arow) * A_LD + akq * 8) = *(const uint4*)(Al + aoff);     \
        bf16* sb = st + 2 * A_PLANE;                                                   \
        _Pragma("unroll")                                                              \
        for (int j = 0; j < 2; j++) {                                                  \
            int idx = j * 256 + tid;                                                   \
            int row = idx >> 4, nq = idx & 15;                                         \
            size_t boff = (size_t)((kc0) + row) * 4096 + n0 + nq * 8;                  \
            *(uint4*)(sb + row * B_LD + nq * 8)        = *(const uint4*)(Bh + boff);   \
            *(uint4*)(sb + (32 + row) * B_LD + nq * 8) = *(const uint4*)(Bl + boff);   \
        }                                                                              \
    } while (0)

    LOADCPY(0, kbase);
    __syncthreads();
    int nk = Kper >> 5;
    for (int kt = 0; kt < nk; kt++) {
        int buf = kt & 1;
        if (kt + 1 < nk) LOADCPY(buf ^ 1, kbase + ((kt + 1) << 5));

        const bf16* st = sm + buf * STAGE_ELEMS;
        const bf16* Ahs = st;
        const bf16* Als = st + A_PLANE;
        const bf16* Bhs = st + 2 * A_PLANE;
        const bf16* Bls = Bhs + B_PLANE;
#pragma unroll
        for (int ks = 0; ks < 2; ks++) {
            wmma::fragment<wmma::matrix_a, 16, 16, 16, bf16, wmma::row_major> a_hi[2], a_lo[2];
            wmma::fragment<wmma::matrix_b, 16, 16, 16, bf16, wmma::row_major> b_hi[2], b_lo[2];
#pragma unroll
            for (int i = 0; i < 2; i++) {
                wmma::load_matrix_sync(a_hi[i], Ahs + (wm * 32 + i * 16) * A_LD + ks * 16, A_LD);
                wmma::load_matrix_sync(a_lo[i], Als + (wm * 32 + i * 16) * A_LD + ks * 16, A_LD);
            }
#pragma unroll
            for (int j = 0; j < 2; j++) {
                wmma::load_matrix_sync(b_hi[j], Bhs + (ks * 16) * B_LD + wn * 32 + j * 16, B_LD);
                wmma::load_matrix_sync(b_lo[j], Bls + (ks * 16) * B_LD + wn * 32 + j * 16, B_LD);
            }
#pragma unroll
            for (int i = 0; i < 2; i++)
#pragma unroll
                for (int j = 0; j < 2; j++) {
                    wmma::mma_sync(acc[i][j], a_hi[i], b_hi[j], acc[i][j]);
                    wmma::mma_sync(acc[i][j], a_hi[i], b_lo[j], acc[i][j]);
                    wmma::mma_sync(acc[i][j], a_lo[i], b_hi[j], acc[i][j]);
                }
        }
        __syncthreads();
    }
#pragma unroll
    for (int i = 0; i < 2; i++)
#pragma unroll
        for (int j = 0; j < 2; j++)
            wmma::store_matrix_sync(C + (size_t)(bm + wm * 32 + i * 16) * 4096 + n0 + wn * 32 + j * 16,
                                    acc[i][j], 4096, wmma::mem_row_major);
#undef LOADCPY
}

// ---------------- reduce K-split + bias + relu -> bf16 planes (fc6) ----------------
__global__ void reduce_planes_kernel(const float* __restrict__ p, const float* __restrict__ bias,
                                     bf16* __restrict__ oh, bf16* __restrict__ ol) {
    int i = blockIdx.x * 256 + threadIdx.x;
    float v = p[i] + p[i + 1572864] + bias[i & 4095];
    v = fmaxf(v, 0.f);
    bf16 h = __float2bfloat16_rn(v);
    oh[i] = h;
    ol[i] = __float2bfloat16_rn(v - __bfloat162float(h));
}

// ---------------- reduce K-split + bias + relu -> f32 (fc7) ----------------
__global__ void reduce_f32_kernel(const float* __restrict__ p, const float* __restrict__ bias,
                                  float* __restrict__ o) {
    int i = blockIdx.x * 256 + threadIdx.x;
    float v = p[i] + p[i + 1572864] + bias[i & 4095];
    o[i] = fmaxf(v, 0.f);
}

// ---------------- head: 4 rows per block ----------------
__global__ void __launch_bounds__(128) head4_kernel(const float* __restrict__ fc7,
                                                    const float* __restrict__ Ws,
                                                    const float* __restrict__ bs,
                                                    const float* __restrict__ Wp,
                                                    const float* __restrict__ bp,
                                                    float* __restrict__ out) {
    extern __shared__ float s[];
    int r0 = blockIdx.x * 4;
    const float4* src = (const float4*)(fc7 + (size_t)r0 * 4096);
    for (int i = threadIdx.x; i < 4096; i += 128) ((float4*)s)[i] = src[i];
    __syncthreads();
    int c = threadIdx.x;
    if (c >= 105) return;
    const float* W;
    int stride;
    float bias;
    if (c < 84) { W = Wp + c; stride = 84; bias = bp[c]; }
    else        { W = Ws + (c - 84); stride = 21; bias = bs[c - 84]; }
    float a0 = 0.f, a1 = 0.f, a2 = 0.f, a3 = 0.f;
#pragma unroll 4
    for (int k = 0; k < 4096; k++) {
        float w = W[(size_t)k * stride];
        a0 = fmaf(s[k], w, a0);
        a1 = fmaf(s[4096 + k], w, a1);
        a2 = fmaf(s[8192 + k], w, a2);
        a3 = fmaf(s[12288 + k], w, a3);
    }
    if (c < 84) {
        out[(r0 + 0) * 84 + c] = a0 + bias;
        out[(r0 + 1) * 84 + c] = a1 + bias;
        out[(r0 + 2) * 84 + c] = a2 + bias;
        out[(r0 + 3) * 84 + c] = a3 + bias;
    } else {
        int cc = c - 84;
        out[25200 + (r0 + 0) * 21 + cc] = a0 + bias;
        out[25200 + (r0 + 1) * 21 + cc] = a1 + bias;
        out[25200 + (r0 + 2) * 21 + cc] = a2 + bias;
        out[25200 + (r0 + 3) * 21 + cc] = a3 + bias;
    }
}

// ---------------- launch ----------------
extern "C" void kernel_launch(void* const* d_in, const int* in_sizes, int n_in,
                              void* d_out, int out_size) {
    const float* x    = (const float*)d_in[0];
    const float* rois = (const float*)d_in[1];
    const int*   ridx = (const int*)d_in[2];
    const float* W1   = (const float*)d_in[3];
    const float* b1   = (const float*)d_in[4];
    const float* W2   = (const float*)d_in[5];
    const float* b2   = (const float*)d_in[6];
    const float* Ws   = (const float*)d_in[7];
    const float* bs   = (const float*)d_in[8];
    const float* Wp   = (const float*)d_in[9];
    const float* bp   = (const float*)d_in[10];
    float* out = (float*)d_out;

    void *pPh, *pPl, *pW1h, *pW1l, *pW2h, *pW2l, *pF6h, *pF6l, *pF7, *pPart;
    cudaGetSymbolAddress(&pPh, g_poolh);   cudaGetSymbolAddress(&pPl, g_pooll);
    cudaGetSymbolAddress(&pW1h, g_W1h);    cudaGetSymbolAddress(&pW1l, g_W1l);
    cudaGetSymbolAddress(&pW2h, g_W2h);    cudaGetSymbolAddress(&pW2l, g_W2l);
    cudaGetSymbolAddress(&pF6h, g_fc6h);   cudaGetSymbolAddress(&pF6l, g_fc6l);
    cudaGetSymbolAddress(&pF7, g_fc7);     cudaGetSymbolAddress(&pPart, g_part);

    const int GEMM_SMEM = STAGE_ELEMS * 2 * 2;   // 55,296 bytes
    cudaFuncSetAttribute(gemm_wmma_kernel, cudaFuncAttributeMaxDynamicSharedMemorySize, GEMM_SMEM);
    cudaFuncSetAttribute(head4_kernel, cudaFuncAttributeMaxDynamicSharedMemorySize, 65536);

    convW_kernel<<<(25088 * 4096 / 4) / 256, 256>>>(W1, (bf16*)pW1h, (bf16*)pW1l, 25088 * 4096 / 4);
    convW_kernel<<<(4096 * 4096 / 4) / 256, 256>>>(W2, (bf16*)pW2h, (bf16*)pW2l, 4096 * 4096 / 4);
    roipool_kernel<<<dim3(384, 4), 256>>>(x, rois, ridx);

    gemm_wmma_kernel<<<dim3(32, 6, 2), 256, GEMM_SMEM>>>(
        (const bf16*)pPh, (const bf16*)pPl, (const bf16*)pW1h, (const bf16*)pW1l,
        (float*)pPart, 25088, 12544);
    reduce_planes_kernel<<<6144, 256>>>((const float*)pPart, b1, (bf16*)pF6h, (bf16*)pF6l);

    gemm_wmma_kernel<<<dim3(32, 6, 2), 256, GEMM_SMEM>>>(
        (const bf16*)pF6h, (const bf16*)pF6l, (const bf16*)pW2h, (const bf16*)pW2l,
        (float*)pPart, 4096, 2048);
    reduce_f32_kernel<<<6144, 256>>>((const float*)pPart, b2, (float*)pF7);

    head4_kernel<<<75, 128, 65536>>>((const float*)pF7, Ws, bs, Wp, bp, out);
}

// round 10
// speedup vs baseline: 2.5475x; 1.0426x over previous
#include <cuda_runtime.h>
#include <cuda_bf16.h>
#include <mma.h>
#include <cstdint>

using namespace nvcuda;
using bf16 = __nv_bfloat16;

// ---------------- scratch (device globals; no allocs) ----------------
__device__ bf16  g_poolh[320 * 25088];
__device__ bf16  g_pooll[320 * 25088];
__device__ bf16  g_W1h[25088 * 4096];
__device__ bf16  g_W1l[25088 * 4096];
__device__ bf16  g_W2h[4096 * 4096];
__device__ bf16  g_W2l[4096 * 4096];
__device__ bf16  g_fc6h[320 * 4096];
__device__ bf16  g_fc6l[320 * 4096];
__device__ float g_fc7[320 * 4096];
__device__ float g_part[2 * 320 * 4096];

__device__ __forceinline__ uint32_t pack_hi(float f0, float f1) {
    uint32_t r;
    asm("cvt.rn.bf16x2.f32 %0, %1, %2;" : "=r"(r) : "f"(f1), "f"(f0));  // low=bf16(f0)
    return r;
}
__device__ __forceinline__ void cpa16(uint32_t dst, const void* src) {
    asm volatile("cp.async.cg.shared.global [%0], [%1], 16;" :: "r"(dst), "l"(src) : "memory");
}
__device__ __forceinline__ void cpa_commit() { asm volatile("cp.async.commit_group;" ::: "memory"); }
template <int N> __device__ __forceinline__ void cpa_wait() {
    asm volatile("cp.async.wait_group %0;" :: "n"(N) : "memory");
}

// ---------------- weight fp32 -> bf16 hi/lo planes ----------------
__global__ void convW_kernel(const float* __restrict__ W, bf16* __restrict__ Wh,
                             bf16* __restrict__ Wl, int n4) {
    int i = blockIdx.x * 256 + threadIdx.x;
    if (i >= n4) return;
    float4 w = ((const float4*)W)[i];
    uint32_t h01 = pack_hi(w.x, w.y), h23 = pack_hi(w.z, w.w);
    float l0 = w.x - __uint_as_float(h01 << 16);
    float l1 = w.y - __uint_as_float(h01 & 0xFFFF0000u);
    float l2 = w.z - __uint_as_float(h23 << 16);
    float l3 = w.w - __uint_as_float(h23 & 0xFFFF0000u);
    ((uint2*)Wh)[i] = make_uint2(h01, h23);
    ((uint2*)Wl)[i] = make_uint2(pack_hi(l0, l1), pack_hi(l2, l3));
}

// ---------------- ROI max pool -> bf16 hi/lo planes ----------------
__global__ void roipool_kernel(const float* __restrict__ x, const float* __restrict__ rois,
                               const int* __restrict__ ridx) {
    int m = blockIdx.x, cg = blockIdx.y;
    size_t ob = (size_t)m * 25088 + (size_t)cg * 128 * 49;
    if (m >= 300) {
        for (int u = threadIdx.x; u < 128 * 49; u += 256) {
            g_poolh[ob + u] = __float2bfloat16_rn(0.f);
            g_pooll[ob + u] = __float2bfloat16_rn(0.f);
        }
        return;
    }
    float y1 = rois[m * 4 + 0], x1 = rois[m * 4 + 1];
    float y2 = rois[m * 4 + 2], x2 = rois[m * 4 + 3];
    int bi = ridx[m];
    int sh_ = (int)rintf(y1 * 0.0625f), sw_ = (int)rintf(x1 * 0.0625f);
    int eh_ = (int)rintf(y2 * 0.0625f), ew_ = (int)rintf(x2 * 0.0625f);
    const float INV7 = 1.0f / 7.0f;   // XLA reciprocal-multiply; bit-exact match required
    float bh = fmaxf((float)(eh_ - sh_ + 1), 1.f) * INV7;
    float bw = fmaxf((float)(ew_ - sw_ + 1), 1.f) * INV7;
    const float* fm = x + (size_t)bi * 512 * 1900;
    for (int u = threadIdx.x; u < 1568; u += 256) {
        int bin = u % 49, cq = u / 49;
        int ph = bin / 7, pw = bin % 7;
        int hs = min(max((int)floorf((float)ph * bh) + sh_, 0), 38);
        int he = min(max((int)ceilf((float)(ph + 1) * bh) + sh_, 0), 38);
        int ws = min(max((int)floorf((float)pw * bw) + sw_, 0), 50);
        int we = min(max((int)ceilf((float)(pw + 1) * bw) + sw_, 0), 50);
        int c = cg * 128 + cq * 4;
        const float* f0 = fm + (size_t)c * 1900;
        float m0 = -1e30f, m1 = -1e30f, m2 = -1e30f, m3 = -1e30f;
        for (int y = hs; y < he; y++)
            for (int xx = ws; xx < we; xx++) {
                int idx = y * 50 + xx;
                m0 = fmaxf(m0, f0[idx]);
                m1 = fmaxf(m1, f0[idx + 1900]);
                m2 = fmaxf(m2, f0[idx + 3800]);
                m3 = fmaxf(m3, f0[idx + 5700]);
            }
        bool ok = (he > hs) && (we > ws);
        float v[4] = { ok ? m0 : 0.f, ok ? m1 : 0.f, ok ? m2 : 0.f, ok ? m3 : 0.f };
#pragma unroll
        for (int i = 0; i < 4; i++) {
            bf16 h = __float2bfloat16_rn(v[i]);
            g_poolh[ob + (cq * 4 + i) * 49 + bin] = h;
            g_pooll[ob + (cq * 4 + i) * 49 + bin] = __float2bfloat16_rn(v[i] - __bfloat162float(h));
        }
    }
}

// ---------------- split-bf16 wmma GEMM with K-split, cp.async pipeline ----------------
#define A_LD 40
#define B_LD 136
#define A_PLANE (64 * A_LD)     // 2560 elems per plane
#define B_PLANE (32 * B_LD)     // 4352
#define STAGE_ELEMS (2 * A_PLANE + 2 * B_PLANE)   // 13824 elems
#define STAGE_BYTES (STAGE_ELEMS * 2)             // 27648 B

__global__ void __launch_bounds__(256, 3) gemm_wmma_kernel(
        const bf16* __restrict__ Ah, const bf16* __restrict__ Al,
        const bf16* __restrict__ Bh, const bf16* __restrict__ Bl,
        float* __restrict__ part, int K, int Kper) {
    extern __shared__ char smraw[];
    bf16* sm = (bf16*)smraw;
    uint32_t smb = (uint32_t)__cvta_generic_to_shared(smraw);

    int tid = threadIdx.x, wid = tid >> 5;
    int wm = wid >> 2, wn = wid & 3;              // 2 x 4 warps, each 32x32
    int n0 = blockIdx.x * 128, bm = blockIdx.y * 64;
    int kbase = blockIdx.z * Kper;
    float* C = part + (size_t)blockIdx.z * 320 * 4096;

    int arow = tid >> 2, akq = tid & 3;

    wmma::fragment<wmma::accumulator, 16, 16, 16, float> acc[2][2];
#pragma unroll
    for (int i = 0; i < 2; i++)
#pragma unroll
        for (int j = 0; j < 2; j++) wmma::fill_fragment(acc[i][j], 0.f);

#define LOADCPY(buf, kc0)                                                              \
    do {                                                                               \
        uint32_t st = smb + (buf) * STAGE_BYTES;                                       \
        size_t aoff = (size_t)(bm + arow) * K + (kc0) + akq * 8;                       \
        cpa16(st + (arow * A_LD + akq * 8) * 2, Ah + aoff);                            \
        cpa16(st + ((64 + arow) * A_LD + akq * 8) * 2, Al + aoff);                     \
        uint32_t sb = st + 2 * A_PLANE * 2;                                            \
        _Pragma("unroll")                                                              \
        for (int j = 0; j < 2; j++) {                                                  \
            int idx = j * 256 + tid;                                                   \
            int row = idx >> 4, nq = idx & 15;                                         \
            size_t boff = (size_t)((kc0) + row) * 4096 + n0 + nq * 8;                  \
            cpa16(sb + (row * B_LD + nq * 8) * 2, Bh + boff);                          \
            cpa16(sb + ((32 + row) * B_LD + nq * 8) * 2, Bl + boff);                   \
        }                                                                              \
        cpa_commit();                                                                  \
    } while (0)

    LOADCPY(0, kbase);
    int nk = Kper >> 5;
    for (int kt = 0; kt < nk; kt++) {
        int buf = kt & 1;
        if (kt + 1 < nk) { LOADCPY(buf ^ 1, kbase + ((kt + 1) << 5)); cpa_wait<1>(); }
        else             { cpa_wait<0>(); }
        __syncthreads();

        const bf16* st = sm + buf * STAGE_ELEMS;
        const bf16* Ahs = st;
        const bf16* Als = st + A_PLANE;
        const bf16* Bhs = st + 2 * A_PLANE;
        const bf16* Bls = Bhs + B_PLANE;
#pragma unroll
        for (int ks = 0; ks < 2; ks++) {
            wmma::fragment<wmma::matrix_a, 16, 16, 16, bf16, wmma::row_major> a_hi[2], a_lo[2];
            wmma::fragment<wmma::matrix_b, 16, 16, 16, bf16, wmma::row_major> b_hi[2], b_lo[2];
#pragma unroll
            for (int i = 0; i < 2; i++) {
                wmma::load_matrix_sync(a_hi[i], Ahs + (wm * 32 + i * 16) * A_LD + ks * 16, A_LD);
                wmma::load_matrix_sync(a_lo[i], Als + (wm * 32 + i * 16) * A_LD + ks * 16, A_LD);
            }
#pragma unroll
            for (int j = 0; j < 2; j++) {
                wmma::load_matrix_sync(b_hi[j], Bhs + (ks * 16) * B_LD + wn * 32 + j * 16, B_LD);
                wmma::load_matrix_sync(b_lo[j], Bls + (ks * 16) * B_LD + wn * 32 + j * 16, B_LD);
            }
#pragma unroll
            for (int i = 0; i < 2; i++)
#pragma unroll
                for (int j = 0; j < 2; j++) {
                    wmma::mma_sync(acc[i][j], a_hi[i], b_hi[j], acc[i][j]);
                    wmma::mma_sync(acc[i][j], a_hi[i], b_lo[j], acc[i][j]);
                    wmma::mma_sync(acc[i][j], a_lo[i], b_hi[j], acc[i][j]);
                }
        }
        __syncthreads();
    }
#pragma unroll
    for (int i = 0; i < 2; i++)
#pragma unroll
        for (int j = 0; j < 2; j++)
            wmma::store_matrix_sync(C + (size_t)(bm + wm * 32 + i * 16) * 4096 + n0 + wn * 32 + j * 16,
                                    acc[i][j], 4096, wmma::mem_row_major);
#undef LOADCPY
}

// ---------------- reduce K-split + bias + relu ----------------
__global__ void reduce_planes_kernel(const float* __restrict__ p, const float* __restrict__ bias,
                                     bf16* __restrict__ oh, bf16* __restrict__ ol) {
    int i = blockIdx.x * 256 + threadIdx.x;
    float v = p[i] + p[i + 1310720] + bias[i & 4095];
    v = fmaxf(v, 0.f);
    bf16 h = __float2bfloat16_rn(v);
    oh[i] = h;
    ol[i] = __float2bfloat16_rn(v - __bfloat162float(h));
}
__global__ void reduce_f32_kernel(const float* __restrict__ p, const float* __restrict__ bias,
                                  float* __restrict__ o) {
    int i = blockIdx.x * 256 + threadIdx.x;
    float v = p[i] + p[i + 1310720] + bias[i & 4095];
    o[i] = fmaxf(v, 0.f);
}

// ---------------- head: 4 rows per block ----------------
__global__ void __launch_bounds__(128) head4_kernel(const float* __restrict__ fc7,
                                                    const float* __restrict__ Ws,
                                                    const float* __restrict__ bs,
                                                    const float* __restrict__ Wp,
                                                    const float* __restrict__ bp,
                                                    float* __restrict__ out) {
    extern __shared__ float s[];
    int r0 = blockIdx.x * 4;
    const float4* src = (const float4*)(fc7 + (size_t)r0 * 4096);
    for (int i = threadIdx.x; i < 4096; i += 128) ((float4*)s)[i] = src[i];
    __syncthreads();
    int c = threadIdx.x;
    if (c >= 105) return;
    const float* W;
    int stride;
    float bias;
    if (c < 84) { W = Wp + c; stride = 84; bias = bp[c]; }
    else        { W = Ws + (c - 84); stride = 21; bias = bs[c - 84]; }
    float a0 = 0.f, a1 = 0.f, a2 = 0.f, a3 = 0.f;
#pragma unroll 4
    for (int k = 0; k < 4096; k++) {
        float w = W[(size_t)k * stride];
        a0 = fmaf(s[k], w, a0);
        a1 = fmaf(s[4096 + k], w, a1);
        a2 = fmaf(s[8192 + k], w, a2);
        a3 = fmaf(s[12288 + k], w, a3);
    }
    if (c < 84) {
        out[(r0 + 0) * 84 + c] = a0 + bias;
        out[(r0 + 1) * 84 + c] = a1 + bias;
        out[(r0 + 2) * 84 + c] = a2 + bias;
        out[(r0 + 3) * 84 + c] = a3 + bias;
    } else {
        int cc = c - 84;
        out[25200 + (r0 + 0) * 21 + cc] = a0 + bias;
        out[25200 + (r0 + 1) * 21 + cc] = a1 + bias;
        out[25200 + (r0 + 2) * 21 + cc] = a2 + bias;
        out[25200 + (r0 + 3) * 21 + cc] = a3 + bias;
    }
}

// ---------------- launch ----------------
extern "C" void kernel_launch(void* const* d_in, const int* in_sizes, int n_in,
                              void* d_out, int out_size) {
    const float* x    = (const float*)d_in[0];
    const float* rois = (const float*)d_in[1];
    const int*   ridx = (const int*)d_in[2];
    const float* W1   = (const float*)d_in[3];
    const float* b1   = (const float*)d_in[4];
    const float* W2   = (const float*)d_in[5];
    const float* b2   = (const float*)d_in[6];
    const float* Ws   = (const float*)d_in[7];
    const float* bs   = (const float*)d_in[8];
    const float* Wp   = (const float*)d_in[9];
    const float* bp   = (const float*)d_in[10];
    float* out = (float*)d_out;

    void *pPh, *pPl, *pW1h, *pW1l, *pW2h, *pW2l, *pF6h, *pF6l, *pF7, *pPart;
    cudaGetSymbolAddress(&pPh, g_poolh);   cudaGetSymbolAddress(&pPl, g_pooll);
    cudaGetSymbolAddress(&pW1h, g_W1h);    cudaGetSymbolAddress(&pW1l, g_W1l);
    cudaGetSymbolAddress(&pW2h, g_W2h);    cudaGetSymbolAddress(&pW2l, g_W2l);
    cudaGetSymbolAddress(&pF6h, g_fc6h);   cudaGetSymbolAddress(&pF6l, g_fc6l);
    cudaGetSymbolAddress(&pF7, g_fc7);     cudaGetSymbolAddress(&pPart, g_part);

    const int GEMM_SMEM = STAGE_BYTES * 2;   // 55,296 bytes
    cudaFuncSetAttribute(gemm_wmma_kernel, cudaFuncAttributeMaxDynamicSharedMemorySize, GEMM_SMEM);
    cudaFuncSetAttribute(head4_kernel, cudaFuncAttributeMaxDynamicSharedMemorySize, 65536);

    convW_kernel<<<(25088 * 4096 / 4) / 256, 256>>>(W1, (bf16*)pW1h, (bf16*)pW1l, 25088 * 4096 / 4);
    convW_kernel<<<(4096 * 4096 / 4) / 256, 256>>>(W2, (bf16*)pW2h, (bf16*)pW2l, 4096 * 4096 / 4);
    roipool_kernel<<<dim3(320, 4), 256>>>(x, rois, ridx);

    gemm_wmma_kernel<<<dim3(32, 5, 2), 256, GEMM_SMEM>>>(
        (const bf16*)pPh, (const bf16*)pPl, (const bf16*)pW1h, (const bf16*)pW1l,
        (float*)pPart, 25088, 12544);
    reduce_planes_kernel<<<5120, 256>>>((const float*)pPart, b1, (bf16*)pF6h, (bf16*)pF6l);

    gemm_wmma_kernel<<<dim3(32, 5, 2), 256, GEMM_SMEM>>>(
        (const bf16*)pF6h, (const bf16*)pF6l, (const bf16*)pW2h, (const bf16*)pW2l,
        (float*)pPart, 4096, 2048);
    reduce_f32_kernel<<<5120, 256>>>((const float*)pPart, b2, (float*)pF7);

    head4_kernel<<<75, 128, 65536>>>((const float*)pF7, Ws, bs, Wp, bp, out);
}